// round 2
// baseline (speedup 1.0000x reference)
#include <cuda_runtime.h>
#include <math_constants.h>

#define BB 4
#define VV 4096
#define FF 64
#define SS 4
#define KN 39            // neighbours kept (K_NEIGHBOURS=40 includes self)
#define OUTF 64
#define TPB 128
#define BND_MAX 64

// Scratch (device globals; no allocation allowed)
__device__ float g_coords[BB * VV * 4];     // (b, v, 4) — float4-aligned rows
__device__ float g_feats[BB * VV * FF];     // (b, v, 64)

// ---------------------------------------------------------------------------
// Kernel 1: coords = x@Ws + bs, feats = x@Wf + bf
// One block (64 threads) per vertex. Wf column loads are coalesced across f.
// ---------------------------------------------------------------------------
__global__ void __launch_bounds__(64) prep_kernel(
    const float* __restrict__ x,
    const float* __restrict__ Wf, const float* __restrict__ bf,
    const float* __restrict__ Ws, const float* __restrict__ bs)
{
    const int vtx = blockIdx.x;        // 0 .. B*V-1
    const int f   = threadIdx.x;       // 0 .. 63
    __shared__ float sx[FF];
    sx[f] = x[vtx * FF + f];
    __syncthreads();

    float acc = bf[f];
#pragma unroll
    for (int k = 0; k < FF; ++k)
        acc = fmaf(sx[k], Wf[k * FF + f], acc);
    g_feats[vtx * FF + f] = acc;

    if (f < SS) {
        float c = bs[f];
#pragma unroll
        for (int k = 0; k < FF; ++k)
            c = fmaf(sx[k], Ws[k * SS + f], c);
        g_coords[vtx * 4 + f] = c;
    }
}

// ---------------------------------------------------------------------------
// Kernel 2: per-query kNN select (exact, radix-histogram) + weighted max/mean
// aggregation + output GEMM + tanh. One block (128 threads) per query vertex.
// ---------------------------------------------------------------------------
__global__ void __launch_bounds__(TPB) grav_kernel(
    const float* __restrict__ x,
    const float* __restrict__ Wo, const float* __restrict__ bo,
    float* __restrict__ out)
{
    const int v    = blockIdx.x;       // vertex within batch
    const int b    = blockIdx.y;       // batch
    const int tid  = threadIdx.x;
    const int base = b * VV;

    __shared__ float s_d2[VV];                 // 16 KB
    __shared__ unsigned s_hist[256];
    __shared__ float s_xq[FF];
    __shared__ int   s_nidx[KN + 1];
    __shared__ float s_nd2[KN + 1];
    __shared__ float s_nw[KN + 1];
    __shared__ float s_coll[128];              // [max(64) | mean(64)]
    __shared__ unsigned long long s_bnd[BND_MAX];
    __shared__ unsigned long long s_red[4];
    __shared__ unsigned long long s_win;
    __shared__ int s_cdef, s_cbnd, s_estar, s_bprefix, s_c;

    const float4* cb = reinterpret_cast<const float4*>(g_coords) + base;
    const float4 cq = cb[v];

    if (tid < FF) s_xq[tid] = x[(base + v) * FF + tid];
    s_hist[tid] = 0u;
    s_hist[tid + 128] = 0u;
    __syncthreads();

    // ---- Pass 1: distances + level-1 histogram on exponent byte ----
    for (int i = tid; i < VV; i += TPB) {
        float4 cu = cb[i];
        float dx = cq.x - cu.x, dy = cq.y - cu.y;
        float dz = cq.z - cu.z, dw = cq.w - cu.w;
        float d2 = fmaf(dx, dx, fmaf(dy, dy, fmaf(dz, dz, dw * dw)));
        if (i == v) {
            s_d2[i] = CUDART_INF_F;            // exclude self
        } else {
            s_d2[i] = d2;
            atomicAdd(&s_hist[__float_as_uint(d2) >> 23], 1u);
        }
    }
    __syncthreads();

    if (tid == 0) {
        int cum = 0, estar = 255, c1 = 0;
        for (int bi = 0; bi < 256; ++bi) {
            int nc = cum + (int)s_hist[bi];
            if (nc >= KN) { estar = bi; c1 = cum; break; }
            cum = nc;
        }
        s_estar = estar; s_c = c1;
    }
    __syncthreads();
    const int estar = s_estar;
    const int c1 = s_c;

    // ---- Pass 2: level-2 histogram on top-8 mantissa bits within estar ----
    s_hist[tid] = 0u;
    s_hist[tid + 128] = 0u;
    __syncthreads();
    for (int i = tid; i < VV; i += TPB) {
        unsigned u = __float_as_uint(s_d2[i]);
        if ((int)(u >> 23) == estar)
            atomicAdd(&s_hist[(u >> 15) & 0xFF], 1u);
    }
    __syncthreads();

    if (tid == 0) {
        int cum = c1, b2 = 255, c = c1;
        for (int m = 0; m < 256; ++m) {
            int nc = cum + (int)s_hist[m];
            if (nc >= KN) { b2 = m; c = cum; break; }
            cum = nc;
        }
        s_bprefix = (estar << 8) | b2;
        s_c = c;
        s_cdef = 0; s_cbnd = 0;
    }
    __syncthreads();
    const int bprefix = s_bprefix;
    const int c = s_c;                          // definite count (< 39)

    // ---- Pass 3: gather definite + boundary candidates ----
    for (int i = tid; i < VV; i += TPB) {
        unsigned u = __float_as_uint(s_d2[i]);
        int p = (int)(u >> 15);                 // 17-bit order-preserving prefix
        if (p < bprefix) {
            int pos = atomicAdd(&s_cdef, 1);
            s_nidx[pos] = i;
            s_nd2[pos] = s_d2[i];
        } else if (p == bprefix) {
            int pos = atomicAdd(&s_cbnd, 1);
            if (pos < BND_MAX)
                s_bnd[pos] = ((unsigned long long)u << 32) | (unsigned)i;
        }
    }
    __syncthreads();

    const int m = s_cbnd;
    const int r = KN - c;                       // boundary picks needed (>=1)

    if (m <= BND_MAX) {
        // Extract r smallest by (d2, idx) from the small boundary list.
        for (int j = 0; j < r; ++j) {
            unsigned long long lk = (tid < m) ? s_bnd[tid]
                                              : 0xFFFFFFFFFFFFFFFFULL;
#pragma unroll
            for (int o = 16; o > 0; o >>= 1) {
                unsigned long long oth = __shfl_down_sync(0xffffffffu, lk, o);
                lk = (oth < lk) ? oth : lk;
            }
            if ((tid & 31) == 0) s_red[tid >> 5] = lk;
            __syncthreads();
            if (tid == 0) {
                unsigned long long w0 = s_red[0];
                if (s_red[1] < w0) w0 = s_red[1];
                if (s_red[2] < w0) w0 = s_red[2];
                if (s_red[3] < w0) w0 = s_red[3];
                s_win = w0;
                s_nidx[c + j] = (int)(w0 & 0xFFFFFFFFULL);
                s_nd2[c + j]  = __uint_as_float((unsigned)(w0 >> 32));
            }
            __syncthreads();
            if (tid < m && s_bnd[tid] == s_win)
                s_bnd[tid] = 0xFFFFFFFFFFFFFFFFULL;
            __syncthreads();
        }
    } else {
        // Degenerate fallback (massive tie bin): exact extraction over array.
        for (int j = 0; j < r; ++j) {
            unsigned long long lk = 0xFFFFFFFFFFFFFFFFULL;
            for (int i = tid; i < VV; i += TPB) {
                unsigned u = __float_as_uint(s_d2[i]);
                if ((int)(u >> 15) == bprefix) {
                    unsigned long long key =
                        ((unsigned long long)u << 32) | (unsigned)i;
                    if (key < lk) lk = key;
                }
            }
#pragma unroll
            for (int o = 16; o > 0; o >>= 1) {
                unsigned long long oth = __shfl_down_sync(0xffffffffu, lk, o);
                lk = (oth < lk) ? oth : lk;
            }
            if ((tid & 31) == 0) s_red[tid >> 5] = lk;
            __syncthreads();
            if (tid == 0) {
                unsigned long long w0 = s_red[0];
                if (s_red[1] < w0) w0 = s_red[1];
                if (s_red[2] < w0) w0 = s_red[2];
                if (s_red[3] < w0) w0 = s_red[3];
                s_win = w0;
                int widx = (int)(w0 & 0xFFFFFFFFULL);
                s_nidx[c + j] = widx;
                s_nd2[c + j]  = __uint_as_float((unsigned)(w0 >> 32));
                s_d2[widx] = CUDART_INF_F;      // mark consumed
            }
            __syncthreads();
        }
    }

    // ---- Weights ----
    if (tid < KN)
        s_nw[tid] = expf(-10.0f * fabsf(s_nd2[tid]));
    __syncthreads();

    // ---- Weighted neighbour aggregation: max + mean over 39 ----
    if (tid < FF) {
        const float* fb = g_feats + (size_t)base * FF;
        float mx = -CUDART_INF_F;
        float sm = 0.0f;
        for (int j = 0; j < KN; ++j) {
            float val = fb[s_nidx[j] * FF + tid] * s_nw[j];
            mx = fmaxf(mx, val);
            sm += val;
        }
        s_coll[tid]      = mx;
        s_coll[FF + tid] = sm * (1.0f / KN);
    }
    __syncthreads();

    // ---- Output GEMM: [x | max | mean] (192) @ Wo (192x64) + bo, tanh ----
    if (tid < OUTF) {
        float acc = bo[tid];
#pragma unroll
        for (int k = 0; k < FF; ++k)
            acc = fmaf(s_xq[k], Wo[k * OUTF + tid], acc);
#pragma unroll
        for (int k = 0; k < 128; ++k)
            acc = fmaf(s_coll[k], Wo[(FF + k) * OUTF + tid], acc);
        out[(base + v) * OUTF + tid] = tanhf(acc);
    }
}

// ---------------------------------------------------------------------------
extern "C" void kernel_launch(void* const* d_in, const int* in_sizes, int n_in,
                              void* d_out, int out_size)
{
    const float* x  = (const float*)d_in[0];
    const float* Wf = (const float*)d_in[1];
    const float* bf = (const float*)d_in[2];
    const float* Ws = (const float*)d_in[3];
    const float* bs = (const float*)d_in[4];
    const float* Wo = (const float*)d_in[5];
    const float* bo = (const float*)d_in[6];
    float* out = (float*)d_out;

    prep_kernel<<<BB * VV, 64>>>(x, Wf, bf, Ws, bs);

    dim3 grid(VV, BB);
    grav_kernel<<<grid, TPB>>>(x, Wo, bo, out);
}